// round 8
// baseline (speedup 1.0000x reference)
#include <cuda_runtime.h>
#include <cuda_fp16.h>
#include <cstdint>

#define N_AUTHOR 100000
#define N_PAPER  200000
#define N_FIELD  50000
#define N_INST   8000
// combined node space (== output row order): author[0,1e5) field[1e5,1.5e5) inst[1.5e5,1.58e5) paper[1.58e5,3.58e5)
#define N_NODES  358000
#define EDGE_CAP 5100000

// ---------------- static device scratch ----------------
__device__ unsigned g_y[27456000];       // fp16 messages: 858000 rows x 64 halves (32 uints/row)
__device__ unsigned g_deg[858000];       // per-rel dst degree -> invdeg float bits (in place)
__device__ int      g_off[N_NODES + 1];  // CSR offsets
__device__ int      g_cur[N_NODES];      // placement cursors
__device__ int      g_part[512];         // scan partials
__device__ unsigned g_perm[EDGE_CAP];    // per-edge payload: (rel<<20 | y_row)
__device__ float    g_w[90112];          // tf32 weights, 11 blocks of [128x64] row-major

__constant__ int c_DEG_OFF[7]    = {0, 200000, 300000, 500000, 550000, 750000, 758000};
__constant__ int c_Y_ROW[7]      = {0, 100000, 300000, 500000, 700000, 750000, 850000};
__constant__ int c_TYPE_BASE[7]  = {158000, 0, 158000, 100000, 158000, 150000, 0};
// SCALE_BASE[r] = DEG_OFF[r] - TYPE_BASE[r]  (invdeg index = SCALE_BASE[r] + combined_node)
__constant__ int c_SCALE_BASE[7] = {-158000, 200000, 142000, 400000, 392000, 600000, 758000};

struct EdgeSet {
    const int* src[7];
    const int* dst[7];
    int pre[8];   // exclusive prefix of edge counts, pre[7] = total
};

static inline int ceil_div(int a, int b) { return (a + b - 1) / b; }

// ---------------- prep kernels ----------------
// 11 column blocks of 64: [W0 W5 self | W1 W2 W3 self | W4 self | W6 self]
__global__ __launch_bounds__(256) void pack_w_kernel(const float* __restrict__ w,
                                                     const float* __restrict__ sw) {
    int i = blockIdx.x * 256 + threadIdx.x;
    if (i >= 90112) return;
    const int BLK_SRC[11] = {0, 5, 7, 1, 2, 3, 7, 4, 7, 6, 7};
    int blk = i >> 13, r = i & 8191;
    int s = BLK_SRC[blk];
    float v = (s == 7) ? sw[r] : w[s * 8192 + r];
    unsigned t;
    asm("cvt.rna.tf32.f32 %0, %1;" : "=r"(t) : "f"(v));
    g_w[i] = __uint_as_float(t);
}

__global__ __launch_bounds__(256) void zero_kernel() {
    int i = blockIdx.x * 256 + threadIdx.x;
    if (i < 858000) g_deg[i] = 0u;
    if (i < N_NODES) g_cur[i] = 0;
}

// one fused pass over all 7 relations
__global__ __launch_bounds__(256) void count_deg_kernel(EdgeSet es) {
    int idx = blockIdx.x * 256 + threadIdx.x;
    if (idx >= es.pre[7]) return;
    int r = 0;
#pragma unroll
    for (int k = 1; k < 7; ++k) r += (idx >= es.pre[k]);
    int i = idx - es.pre[r];
    atomicAdd(&g_deg[c_DEG_OFF[r] + __ldcs(&es.dst[r][i])], 1u);
}

// combined degree of node i from RAW per-relation counts (before inv_deg overwrites)
__device__ __forceinline__ int combined_deg(int i) {
    if (i < 100000)  return (int)(g_deg[200000 + i] + g_deg[758000 + i]);               // author
    if (i < 150000)  return (int)g_deg[500000 + (i - 100000)];                           // field
    if (i < 158000)  return (int)g_deg[750000 + (i - 150000)];                           // inst
    int d = i - 158000; return (int)(g_deg[d] + g_deg[300000 + d] + g_deg[550000 + d]);  // paper
}

__global__ __launch_bounds__(256) void inv_deg_kernel() {
    int i = blockIdx.x * 256 + threadIdx.x;
    if (i < 858000) {
        unsigned d = g_deg[i];
        g_deg[i] = __float_as_uint(1.0f / (float)(d > 0u ? d : 1u));
    }
}

// ---------------- prefix scan over combined degrees (chunk=1024) ----------------
__global__ __launch_bounds__(256) void scan1_kernel() {
    int b = blockIdx.x, t = threadIdx.x;
    int base = b * 1024, s = 0;
#pragma unroll
    for (int k = 0; k < 4; ++k) {
        int i = base + t * 4 + k;
        if (i < N_NODES) s += combined_deg(i);
    }
    __shared__ int sm[256];
    sm[t] = s; __syncthreads();
    for (int d = 128; d > 0; d >>= 1) { if (t < d) sm[t] += sm[t + d]; __syncthreads(); }
    if (t == 0) g_part[b] = sm[0];
}

__global__ __launch_bounds__(512) void scan2_kernel(int nparts) {
    __shared__ int sm[512];
    int t = threadIdx.x;
    int v = (t < nparts) ? g_part[t] : 0;
    sm[t] = v; __syncthreads();
    for (int d = 1; d < 512; d <<= 1) {
        int x = (t >= d) ? sm[t - d] : 0; __syncthreads();
        sm[t] += x; __syncthreads();
    }
    if (t < nparts) g_part[t] = sm[t] - v;  // exclusive
    if (t == 511) g_off[N_NODES] = sm[511]; // total
}

__global__ __launch_bounds__(1024) void scan3_kernel() {
    int b = blockIdx.x, t = threadIdx.x;
    int i = b * 1024 + t;
    int v = (i < N_NODES) ? combined_deg(i) : 0;
    __shared__ int sm[1024];
    sm[t] = v; __syncthreads();
    for (int d = 1; d < 1024; d <<= 1) {
        int x = (t >= d) ? sm[t - d] : 0; __syncthreads();
        sm[t] += x; __syncthreads();
    }
    if (i < N_NODES) g_off[i] = g_part[b] + sm[t] - v;
}

// ---------------- fused edge placement (payload = rel<<20 | y_row) ----------------
__global__ __launch_bounds__(256) void place_kernel(EdgeSet es) {
    int idx = blockIdx.x * 256 + threadIdx.x;
    if (idx >= es.pre[7]) return;
    int r = 0;
#pragma unroll
    for (int k = 1; k < 7; ++k) r += (idx >= es.pre[k]);
    int i = idx - es.pre[r];
    int d = __ldcs(&es.dst[r][i]);
    int gg = c_TYPE_BASE[r] + d;
    int pos = g_off[gg] + atomicAdd(&g_cur[gg], 1);
    __stcs(&g_perm[pos], ((unsigned)r << 20) | (unsigned)(c_Y_ROW[r] + __ldcs(&es.src[r][i])));
}

// ---------------- single fused tf32 GEMM over all 4 src types ----------------
// CTA = 256 rows (8 warps x 32 rows): each warp computes TWO m16 tiles per nb,
// halving B smem-read bytes per output row vs 16 rows/warp.
struct GemmCfg {
    const float* A[4];
    void*        outp[4][4];  // [type][cb]: unsigned* (fp16 y) or float* (f32 out)
    int          wblk[4];     // first weight block index in g_w
    int          nblk[4];
    int          selfcb[4];   // cb index that is the self-loop (f32 + bias)
    int          M[4];
    int          pre[5];      // CTA prefix per type
};

__global__ __launch_bounds__(256, 1) void gemm_kernel(GemmCfg cfg, const float* __restrict__ bias) {
    __shared__ unsigned Bs[128 * 72];  // stride 72 words: conflict-free frag loads
    const int tid = threadIdx.x, warp = tid >> 5, lane = tid & 31;
    const int g = lane >> 2, tig = lane & 3;

    const int b = blockIdx.x;
    int t = 0;
#pragma unroll
    for (int k = 1; k < 4; ++k) t += (b >= cfg.pre[k]);
    const int row0 = (b - cfg.pre[t]) * 256;
    const int M = cfg.M[t];
    const int nblk = cfg.nblk[t];
    const int selfcb = cfg.selfcb[t];
    const float* wbase = g_w + (size_t)cfg.wblk[t] * 8192;

    const int r0g = row0 + warp * 32 + g;   // tile0 rows: r0g, r0g+8; tile1: +16, +24
    bool va[4];
#pragma unroll
    for (int q = 0; q < 4; ++q) va[q] = (r0g + q * 8) < M;

    // A fragments for both tiles: load + convert once, reuse for every column block
    unsigned ar[2][4][16];
#pragma unroll
    for (int t2 = 0; t2 < 2; ++t2) {
        const float* Aa = cfg.A[t] + (size_t)(r0g + t2 * 16) * 128;
        const float* Ab = Aa + 8 * 128;
        const bool w0 = va[t2 * 2], w1 = va[t2 * 2 + 1];
#pragma unroll
        for (int kc = 0; kc < 16; ++kc) {
            const int k0 = kc * 8;
            float f0 = w0 ? __ldg(Aa + k0 + tig)     : 0.f;
            float f2 = w0 ? __ldg(Aa + k0 + tig + 4) : 0.f;
            float f1 = w1 ? __ldg(Ab + k0 + tig)     : 0.f;
            float f3 = w1 ? __ldg(Ab + k0 + tig + 4) : 0.f;
            asm("cvt.rna.tf32.f32 %0, %1;" : "=r"(ar[t2][0][kc]) : "f"(f0));
            asm("cvt.rna.tf32.f32 %0, %1;" : "=r"(ar[t2][1][kc]) : "f"(f1));
            asm("cvt.rna.tf32.f32 %0, %1;" : "=r"(ar[t2][2][kc]) : "f"(f2));
            asm("cvt.rna.tf32.f32 %0, %1;" : "=r"(ar[t2][3][kc]) : "f"(f3));
        }
    }

    for (int cb = 0; cb < nblk; ++cb) {
        __syncthreads();  // previous iteration's Bs reads complete
        const float4* bsrc = (const float4*)(wbase + (size_t)cb * 8192);
#pragma unroll
        for (int it = 0; it < 8; ++it) {
            int idx = it * 256 + tid;        // 0..2047 float4s
            int k = idx >> 4, j4 = idx & 15;
            float4 v = __ldg(bsrc + idx);
            *(float4*)&Bs[k * 72 + j4 * 4] = v;
        }
        __syncthreads();

        float c[2][8][4];
#pragma unroll
        for (int t2 = 0; t2 < 2; ++t2)
#pragma unroll
            for (int nb = 0; nb < 8; nb++)
#pragma unroll
                for (int j = 0; j < 4; j++) c[t2][nb][j] = 0.f;

#pragma unroll
        for (int kc = 0; kc < 16; ++kc) {
            const int k0 = kc * 8;
            unsigned b0[8], b1[8];
#pragma unroll
            for (int nb = 0; nb < 8; ++nb) {
                b0[nb] = Bs[(k0 + tig) * 72 + nb * 8 + g];
                b1[nb] = Bs[(k0 + tig + 4) * 72 + nb * 8 + g];
            }
#pragma unroll
            for (int nb = 0; nb < 8; ++nb) {
#pragma unroll
                for (int t2 = 0; t2 < 2; ++t2) {
                    asm volatile(
                        "mma.sync.aligned.m16n8k8.row.col.f32.tf32.tf32.f32 "
                        "{%0,%1,%2,%3}, {%4,%5,%6,%7}, {%8,%9}, {%0,%1,%2,%3};"
                        : "+f"(c[t2][nb][0]), "+f"(c[t2][nb][1]),
                          "+f"(c[t2][nb][2]), "+f"(c[t2][nb][3])
                        : "r"(ar[t2][0][kc]), "r"(ar[t2][1][kc]),
                          "r"(ar[t2][2][kc]), "r"(ar[t2][3][kc]),
                          "r"(b0[nb]), "r"(b1[nb]));
                }
            }
        }

        if (cb == selfcb) {
            float* C = (float*)cfg.outp[t][cb];
#pragma unroll
            for (int t2 = 0; t2 < 2; ++t2) {
                const int rr = r0g + t2 * 16;
#pragma unroll
                for (int nb = 0; nb < 8; ++nb) {
                    int col = nb * 8 + tig * 2;
                    float b0v = __ldg(&bias[col]), b1v = __ldg(&bias[col + 1]);
                    if (va[t2 * 2])
                        __stcs((float2*)&C[(size_t)rr * 64 + col],
                               make_float2(c[t2][nb][0] + b0v, c[t2][nb][1] + b1v));
                    if (va[t2 * 2 + 1])
                        __stcs((float2*)&C[(size_t)(rr + 8) * 64 + col],
                               make_float2(c[t2][nb][2] + b0v, c[t2][nb][3] + b1v));
                }
            }
        } else {
            unsigned* C = (unsigned*)cfg.outp[t][cb];
#pragma unroll
            for (int t2 = 0; t2 < 2; ++t2) {
                const int rr = r0g + t2 * 16;
#pragma unroll
                for (int nb = 0; nb < 8; ++nb) {
                    int u = nb * 4 + tig;  // uint column index (2 halves)
                    if (va[t2 * 2]) {
                        __half2 h = __float22half2_rn(make_float2(c[t2][nb][0], c[t2][nb][1]));
                        C[(size_t)rr * 32 + u] = *(unsigned*)&h;
                    }
                    if (va[t2 * 2 + 1]) {
                        __half2 h = __float22half2_rn(make_float2(c[t2][nb][2], c[t2][nb][3]));
                        C[(size_t)(rr + 8) * 32 + u] = *(unsigned*)&h;
                    }
                }
            }
        }
    }
}

// ---------------- CSR accumulate + ReLU ----------------
// Warp per node. Lanes cooperatively prefetch 32 edge payloads (coalesced) and
// resolve their scales; shuffles broadcast each (row, scale) so all y-row
// gathers issue independently (deep MLP, no per-edge broadcast-load chain).
__global__ __launch_bounds__(256) void accum_kernel(float2* __restrict__ out2) {
    int node = blockIdx.x * 8 + (threadIdx.x >> 5);
    if (node >= N_NODES) return;
    int l = threadIdx.x & 31;
    int s = g_off[node], e = g_off[node + 1];

    float2 acc = make_float2(0.f, 0.f);
    for (int base = s; base < e; base += 32) {
        int cnt = min(32, e - base);
        unsigned p = (l < cnt) ? __ldcs(&g_perm[base + l]) : 0u;
        float sc = (l < cnt) ? __uint_as_float(g_deg[c_SCALE_BASE[p >> 20] + node]) : 0.f;
        unsigned row = p & 0xFFFFFu;

        int j = 0;
        for (; j + 1 < cnt; j += 2) {
            unsigned r0 = __shfl_sync(0xffffffffu, row, j);
            unsigned r1 = __shfl_sync(0xffffffffu, row, j + 1);
            float s0 = __shfl_sync(0xffffffffu, sc, j);
            float s1 = __shfl_sync(0xffffffffu, sc, j + 1);
            unsigned u0 = __ldg(&g_y[(size_t)r0 * 32 + l]);
            unsigned u1 = __ldg(&g_y[(size_t)r1 * 32 + l]);
            float2 v0 = __half22float2(*(__half2*)&u0);
            float2 v1 = __half22float2(*(__half2*)&u1);
            acc.x += v0.x * s0 + v1.x * s1;
            acc.y += v0.y * s0 + v1.y * s1;
        }
        if (j < cnt) {
            unsigned r0 = __shfl_sync(0xffffffffu, row, j);
            float s0 = __shfl_sync(0xffffffffu, sc, j);
            unsigned u0 = __ldg(&g_y[(size_t)r0 * 32 + l]);
            float2 v0 = __half22float2(*(__half2*)&u0);
            acc.x += v0.x * s0;
            acc.y += v0.y * s0;
        }
    }

    float2 o = __ldcs(&out2[(size_t)node * 32 + l]);  // self-loop + bias from GEMM
    o.x = fmaxf(o.x + acc.x, 0.f);
    o.y = fmaxf(o.y + acc.y, 0.f);
    __stcs(&out2[(size_t)node * 32 + l], o);
}

// ---------------- launch ----------------
static cudaStream_t g_s2;
static cudaEvent_t  g_fork, g_es3, g_join;
static bool         g_streams_ready = false;

extern "C" void kernel_launch(void* const* d_in, const int* in_sizes, int n_in,
                              void* d_out, int out_size) {
    const float* x_author = (const float*)d_in[0];
    const float* x_field  = (const float*)d_in[1];
    const float* x_inst   = (const float*)d_in[2];
    const float* x_paper  = (const float*)d_in[3];
    const float* weight   = (const float*)d_in[4];
    const float* selfw    = (const float*)d_in[5];
    const float* bias     = (const float*)d_in[6];

    EdgeSet es;
    int total = 0;
    for (int r = 0; r < 7; r++) {
        es.src[r] = (const int*)d_in[7 + 2 * r];
        es.dst[r] = (const int*)d_in[8 + 2 * r];
        es.pre[r] = total;
        total += in_sizes[7 + 2 * r];
    }
    es.pre[7] = total;

    float* out = (float*)d_out;
    unsigned* yb;
    cudaGetSymbolAddress((void**)&yb, g_y);

    float* out_author = out;
    float* out_field  = out + (size_t)N_AUTHOR * 64;
    float* out_inst   = out + (size_t)(N_AUTHOR + N_FIELD) * 64;
    float* out_paper  = out + (size_t)(N_AUTHOR + N_FIELD + N_INST) * 64;

    if (!g_streams_ready) {  // first call is uncaptured; handles reused at capture
        cudaStreamCreateWithFlags(&g_s2, cudaStreamNonBlocking);
        cudaEventCreateWithFlags(&g_fork, cudaEventDisableTiming);
        cudaEventCreateWithFlags(&g_es3, cudaEventDisableTiming);
        cudaEventCreateWithFlags(&g_join, cudaEventDisableTiming);
        g_streams_ready = true;
    }

    // ---- fork ----
    cudaEventRecord(g_fork, 0);
    cudaStreamWaitEvent(g_s2, g_fork, 0);

    // launch order note: ncu (-s 5 -c 1) profiles the 4th kernel in code order.
    pack_w_kernel<<<ceil_div(90112, 256), 256, 0, g_s2>>>(weight, selfw);      // 0
    zero_kernel<<<ceil_div(858000, 256), 256>>>();                              // 1
    count_deg_kernel<<<ceil_div(total, 256), 256>>>(es);                        // 2

    GemmCfg cfg;
    cfg.A[0] = x_author; cfg.A[1] = x_paper; cfg.A[2] = x_field; cfg.A[3] = x_inst;
    cfg.M[0] = N_AUTHOR; cfg.M[1] = N_PAPER; cfg.M[2] = N_FIELD; cfg.M[3] = N_INST;
    cfg.wblk[0] = 0; cfg.wblk[1] = 3; cfg.wblk[2] = 7; cfg.wblk[3] = 9;
    cfg.nblk[0] = 3; cfg.nblk[1] = 4; cfg.nblk[2] = 2; cfg.nblk[3] = 2;
    cfg.selfcb[0] = 2; cfg.selfcb[1] = 3; cfg.selfcb[2] = 1; cfg.selfcb[3] = 1;
    cfg.outp[0][0] = yb;                         cfg.outp[0][1] = yb + (size_t)750000 * 32;
    cfg.outp[0][2] = out_author;                 cfg.outp[0][3] = nullptr;
    cfg.outp[1][0] = yb + (size_t)100000 * 32;   cfg.outp[1][1] = yb + (size_t)300000 * 32;
    cfg.outp[1][2] = yb + (size_t)500000 * 32;   cfg.outp[1][3] = out_paper;
    cfg.outp[2][0] = yb + (size_t)700000 * 32;   cfg.outp[2][1] = out_field;
    cfg.outp[2][2] = nullptr;                    cfg.outp[2][3] = nullptr;
    cfg.outp[3][0] = yb + (size_t)850000 * 32;   cfg.outp[3][1] = out_inst;
    cfg.outp[3][2] = nullptr;                    cfg.outp[3][3] = nullptr;
    cfg.pre[0] = 0;
    cfg.pre[1] = cfg.pre[0] + ceil_div(N_AUTHOR, 256);  // 391
    cfg.pre[2] = cfg.pre[1] + ceil_div(N_PAPER, 256);   // +782
    cfg.pre[3] = cfg.pre[2] + ceil_div(N_FIELD, 256);   // +196
    cfg.pre[4] = cfg.pre[3] + ceil_div(N_INST, 256);    // +32
    gemm_kernel<<<cfg.pre[4], 256, 0, g_s2>>>(cfg, bias);                       // 3 <- profiled

    const int nchunks = ceil_div(N_NODES, 1024);  // 350
    scan1_kernel<<<nchunks, 256>>>();                                           // 4
    scan2_kernel<<<1, 512>>>(nchunks);                                          // 5
    scan3_kernel<<<nchunks, 1024>>>();                                          // 6
    cudaEventRecord(g_es3, 0);            // scans done reading raw counts
    cudaStreamWaitEvent(g_s2, g_es3, 0);
    inv_deg_kernel<<<ceil_div(858000, 256), 256, 0, g_s2>>>();                  // 7 (s2)
    place_kernel<<<ceil_div(total, 256), 256>>>(es);                            // 8 (main)
    cudaEventRecord(g_join, g_s2);

    // ---- join, then gather-sum + fused ReLU ----
    cudaStreamWaitEvent(0, g_join, 0);
    accum_kernel<<<ceil_div(N_NODES, 8), 256>>>((float2*)out);                  // 9
}

// round 9
// speedup vs baseline: 1.0174x; 1.0174x over previous
#include <cuda_runtime.h>
#include <cuda_fp16.h>
#include <cstdint>

#define N_AUTHOR 100000
#define N_PAPER  200000
#define N_FIELD  50000
#define N_INST   8000
// combined node space (== output row order): author[0,1e5) field[1e5,1.5e5) inst[1.5e5,1.58e5) paper[1.58e5,3.58e5)
#define N_NODES  358000
#define EDGE_CAP 5100000

// ---------------- static device scratch ----------------
__device__ unsigned g_y[27456000];       // fp16 messages: 858000 rows x 64 halves (32 uints/row)
__device__ unsigned g_deg[858000];       // per-rel dst degree -> invdeg float bits (in place)
__device__ int      g_off[N_NODES + 1];  // CSR offsets
__device__ int      g_cur[N_NODES];      // placement cursors
__device__ int      g_part[512];         // scan partials
__device__ unsigned g_perm[EDGE_CAP];    // per-edge payload: (rel<<20 | y_row)
__device__ float    g_w[90112];          // tf32 weights, 11 blocks, LDS128-friendly word order

__constant__ int c_DEG_OFF[7]    = {0, 200000, 300000, 500000, 550000, 750000, 758000};
__constant__ int c_Y_ROW[7]      = {0, 100000, 300000, 500000, 700000, 750000, 850000};
__constant__ int c_TYPE_BASE[7]  = {158000, 0, 158000, 100000, 158000, 150000, 0};
// SCALE_BASE[r] = DEG_OFF[r] - TYPE_BASE[r]  (invdeg index = SCALE_BASE[r] + combined_node)
__constant__ int c_SCALE_BASE[7] = {-158000, 200000, 142000, 400000, 392000, 600000, 758000};

struct EdgeSet {
    const int* src[7];
    const int* dst[7];
    int pre[8];   // exclusive prefix of edge counts, pre[7] = total
};

static inline int ceil_div(int a, int b) { return (a + b - 1) / b; }

// ---------------- prep kernels ----------------
// dense per-block word order q = g*8 + h*4 + m  (value = B[k][ (h*4+m)*8 + g ]),
// so the GEMM stage's float4 copy lands chunks at 16B-aligned smem slots.
__global__ __launch_bounds__(256) void pack_w_kernel(const float* __restrict__ w,
                                                     const float* __restrict__ sw) {
    int i = blockIdx.x * 256 + threadIdx.x;
    if (i >= 90112) return;
    const int BLK_SRC[11] = {0, 5, 7, 1, 2, 3, 7, 4, 7, 6, 7};
    int blk = i >> 13, rem = i & 8191;
    int k = rem >> 6, q = rem & 63;
    int g2 = q >> 3, h = (q >> 2) & 1, m = q & 3;
    int col = (h * 4 + m) * 8 + g2;
    int s = BLK_SRC[blk];
    float v = (s == 7) ? sw[k * 64 + col] : w[s * 8192 + k * 64 + col];
    unsigned t;
    asm("cvt.rna.tf32.f32 %0, %1;" : "=r"(t) : "f"(v));
    g_w[i] = __uint_as_float(t);
}

__global__ __launch_bounds__(256) void zero_kernel() {
    int i = blockIdx.x * 256 + threadIdx.x;
    if (i < 858000) g_deg[i] = 0u;
    if (i < N_NODES) g_cur[i] = 0;
}

// one fused pass over all 7 relations
__global__ __launch_bounds__(256) void count_deg_kernel(EdgeSet es) {
    int idx = blockIdx.x * 256 + threadIdx.x;
    if (idx >= es.pre[7]) return;
    int r = 0;
#pragma unroll
    for (int k = 1; k < 7; ++k) r += (idx >= es.pre[k]);
    int i = idx - es.pre[r];
    atomicAdd(&g_deg[c_DEG_OFF[r] + __ldcs(&es.dst[r][i])], 1u);
}

// combined degree of node i from RAW per-relation counts (before inv_deg overwrites)
__device__ __forceinline__ int combined_deg(int i) {
    if (i < 100000)  return (int)(g_deg[200000 + i] + g_deg[758000 + i]);               // author
    if (i < 150000)  return (int)g_deg[500000 + (i - 100000)];                           // field
    if (i < 158000)  return (int)g_deg[750000 + (i - 150000)];                           // inst
    int d = i - 158000; return (int)(g_deg[d] + g_deg[300000 + d] + g_deg[550000 + d]);  // paper
}

__global__ __launch_bounds__(256) void inv_deg_kernel() {
    int i = blockIdx.x * 256 + threadIdx.x;
    if (i < 858000) {
        unsigned d = g_deg[i];
        g_deg[i] = __float_as_uint(1.0f / (float)(d > 0u ? d : 1u));
    }
}

// ---------------- prefix scan over combined degrees (chunk=1024) ----------------
__global__ __launch_bounds__(256) void scan1_kernel() {
    int b = blockIdx.x, t = threadIdx.x;
    int base = b * 1024, s = 0;
#pragma unroll
    for (int k = 0; k < 4; ++k) {
        int i = base + t * 4 + k;
        if (i < N_NODES) s += combined_deg(i);
    }
    __shared__ int sm[256];
    sm[t] = s; __syncthreads();
    for (int d = 128; d > 0; d >>= 1) { if (t < d) sm[t] += sm[t + d]; __syncthreads(); }
    if (t == 0) g_part[b] = sm[0];
}

__global__ __launch_bounds__(512) void scan2_kernel(int nparts) {
    __shared__ int sm[512];
    int t = threadIdx.x;
    int v = (t < nparts) ? g_part[t] : 0;
    sm[t] = v; __syncthreads();
    for (int d = 1; d < 512; d <<= 1) {
        int x = (t >= d) ? sm[t - d] : 0; __syncthreads();
        sm[t] += x; __syncthreads();
    }
    if (t < nparts) g_part[t] = sm[t] - v;  // exclusive
    if (t == 511) g_off[N_NODES] = sm[511]; // total
}

__global__ __launch_bounds__(1024) void scan3_kernel() {
    int b = blockIdx.x, t = threadIdx.x;
    int i = b * 1024 + t;
    int v = (i < N_NODES) ? combined_deg(i) : 0;
    __shared__ int sm[1024];
    sm[t] = v; __syncthreads();
    for (int d = 1; d < 1024; d <<= 1) {
        int x = (t >= d) ? sm[t - d] : 0; __syncthreads();
        sm[t] += x; __syncthreads();
    }
    if (i < N_NODES) g_off[i] = g_part[b] + sm[t] - v;
}

// ---------------- fused edge placement (payload = rel<<20 | y_row) ----------------
__global__ __launch_bounds__(256) void place_kernel(EdgeSet es) {
    int idx = blockIdx.x * 256 + threadIdx.x;
    if (idx >= es.pre[7]) return;
    int r = 0;
#pragma unroll
    for (int k = 1; k < 7; ++k) r += (idx >= es.pre[k]);
    int i = idx - es.pre[r];
    int d = __ldcs(&es.dst[r][i]);
    int gg = c_TYPE_BASE[r] + d;
    int pos = g_off[gg] + atomicAdd(&g_cur[gg], 1);
    __stcs(&g_perm[pos], ((unsigned)r << 20) | (unsigned)(c_Y_ROW[r] + __ldcs(&es.src[r][i])));
}

// ---------------- single fused tf32 GEMM over all 4 src types ----------------
// CTA = 256 rows (8 warps x 32 rows). B fragments fetched via conflict-free
// LDS.128: smem word(k, col=nb*8+g) = (k&63)*132 + g*16 + ((k>>6)&1)*8
//                                      + (nb>>2)*4 + (nb&3).
struct GemmCfg {
    const float* A[4];
    void*        outp[4][4];  // [type][cb]: unsigned* (fp16 y) or float* (f32 out)
    int          wblk[4];     // first weight block index in g_w
    int          nblk[4];
    int          selfcb[4];   // cb index that is the self-loop (f32 + bias)
    int          M[4];
    int          pre[5];      // CTA prefix per type
};

__global__ __launch_bounds__(256, 1) void gemm_kernel(GemmCfg cfg, const float* __restrict__ bias) {
    __shared__ unsigned Bs[64 * 132];  // 33792 B
    const int tid = threadIdx.x, warp = tid >> 5, lane = tid & 31;
    const int g = lane >> 2, tig = lane & 3;

    const int b = blockIdx.x;
    int t = 0;
#pragma unroll
    for (int k = 1; k < 4; ++k) t += (b >= cfg.pre[k]);
    const int row0 = (b - cfg.pre[t]) * 256;
    const int M = cfg.M[t];
    const int nblk = cfg.nblk[t];
    const int selfcb = cfg.selfcb[t];
    const float* wbase = g_w + (size_t)cfg.wblk[t] * 8192;

    const int r0g = row0 + warp * 32 + g;   // tile0 rows: r0g, r0g+8; tile1: +16, +24
    bool va[4];
#pragma unroll
    for (int q = 0; q < 4; ++q) va[q] = (r0g + q * 8) < M;

    // A fragments for both tiles: load (.cs, single touch) + convert once
    unsigned ar[2][4][16];
#pragma unroll
    for (int t2 = 0; t2 < 2; ++t2) {
        const float* Aa = cfg.A[t] + (size_t)(r0g + t2 * 16) * 128;
        const float* Ab = Aa + 8 * 128;
        const bool w0 = va[t2 * 2], w1 = va[t2 * 2 + 1];
#pragma unroll
        for (int kc = 0; kc < 16; ++kc) {
            const int k0 = kc * 8;
            float f0 = w0 ? __ldcs(Aa + k0 + tig)     : 0.f;
            float f2 = w0 ? __ldcs(Aa + k0 + tig + 4) : 0.f;
            float f1 = w1 ? __ldcs(Ab + k0 + tig)     : 0.f;
            float f3 = w1 ? __ldcs(Ab + k0 + tig + 4) : 0.f;
            asm("cvt.rna.tf32.f32 %0, %1;" : "=r"(ar[t2][0][kc]) : "f"(f0));
            asm("cvt.rna.tf32.f32 %0, %1;" : "=r"(ar[t2][1][kc]) : "f"(f1));
            asm("cvt.rna.tf32.f32 %0, %1;" : "=r"(ar[t2][2][kc]) : "f"(f2));
            asm("cvt.rna.tf32.f32 %0, %1;" : "=r"(ar[t2][3][kc]) : "f"(f3));
        }
    }

    for (int cb = 0; cb < nblk; ++cb) {
        __syncthreads();  // previous iteration's Bs reads complete
        const float4* bsrc = (const float4*)(wbase + (size_t)cb * 8192);
#pragma unroll
        for (int it = 0; it < 8; ++it) {
            int c = it * 256 + tid;          // 0..2047 float4 chunks
            int k = c >> 4, j = c & 15;      // j = g2*2 + h
            float4 v = __ldg(bsrc + c);
            int dw = (k & 63) * 132 + (j >> 1) * 16 + ((k >> 6) & 1) * 8 + (j & 1) * 4;
            *(float4*)&Bs[dw] = v;
        }
        __syncthreads();

        float c[2][8][4];
#pragma unroll
        for (int t2 = 0; t2 < 2; ++t2)
#pragma unroll
            for (int nb = 0; nb < 8; nb++)
#pragma unroll
                for (int j = 0; j < 4; j++) c[t2][nb][j] = 0.f;

#pragma unroll
        for (int kc = 0; kc < 16; ++kc) {
            const int kk = kc * 8 + tig;
            const int base  = (kk & 63) * 132 + g * 16 + ((kk >> 6) & 1) * 8;
            const int base4 = base + 4 * 132;   // kk+4: same 64-half (k0 multiple of 8)
            uint4 qa0 = *(uint4*)&Bs[base];
            uint4 qa1 = *(uint4*)&Bs[base + 4];
            uint4 qb0 = *(uint4*)&Bs[base4];
            uint4 qb1 = *(uint4*)&Bs[base4 + 4];
            unsigned b0[8] = {qa0.x, qa0.y, qa0.z, qa0.w, qa1.x, qa1.y, qa1.z, qa1.w};
            unsigned b1[8] = {qb0.x, qb0.y, qb0.z, qb0.w, qb1.x, qb1.y, qb1.z, qb1.w};
#pragma unroll
            for (int nb = 0; nb < 8; ++nb) {
#pragma unroll
                for (int t2 = 0; t2 < 2; ++t2) {
                    asm volatile(
                        "mma.sync.aligned.m16n8k8.row.col.f32.tf32.tf32.f32 "
                        "{%0,%1,%2,%3}, {%4,%5,%6,%7}, {%8,%9}, {%0,%1,%2,%3};"
                        : "+f"(c[t2][nb][0]), "+f"(c[t2][nb][1]),
                          "+f"(c[t2][nb][2]), "+f"(c[t2][nb][3])
                        : "r"(ar[t2][0][kc]), "r"(ar[t2][1][kc]),
                          "r"(ar[t2][2][kc]), "r"(ar[t2][3][kc]),
                          "r"(b0[nb]), "r"(b1[nb]));
                }
            }
        }

        if (cb == selfcb) {
            float* C = (float*)cfg.outp[t][cb];
#pragma unroll
            for (int t2 = 0; t2 < 2; ++t2) {
                const int rr = r0g + t2 * 16;
#pragma unroll
                for (int nb = 0; nb < 8; ++nb) {
                    int col = nb * 8 + tig * 2;
                    float b0v = __ldg(&bias[col]), b1v = __ldg(&bias[col + 1]);
                    if (va[t2 * 2])
                        __stcs((float2*)&C[(size_t)rr * 64 + col],
                               make_float2(c[t2][nb][0] + b0v, c[t2][nb][1] + b1v));
                    if (va[t2 * 2 + 1])
                        __stcs((float2*)&C[(size_t)(rr + 8) * 64 + col],
                               make_float2(c[t2][nb][2] + b0v, c[t2][nb][3] + b1v));
                }
            }
        } else {
            unsigned* C = (unsigned*)cfg.outp[t][cb];
#pragma unroll
            for (int t2 = 0; t2 < 2; ++t2) {
                const int rr = r0g + t2 * 16;
#pragma unroll
                for (int nb = 0; nb < 8; ++nb) {
                    int u = nb * 4 + tig;  // uint column index (2 halves)
                    if (va[t2 * 2]) {
                        __half2 h = __float22half2_rn(make_float2(c[t2][nb][0], c[t2][nb][1]));
                        C[(size_t)rr * 32 + u] = *(unsigned*)&h;
                    }
                    if (va[t2 * 2 + 1]) {
                        __half2 h = __float22half2_rn(make_float2(c[t2][nb][2], c[t2][nb][3]));
                        C[(size_t)(rr + 8) * 32 + u] = *(unsigned*)&h;
                    }
                }
            }
        }
    }
}

// ---------------- CSR accumulate + ReLU ----------------
// Warp per node. Lanes cooperatively prefetch 32 edge payloads (coalesced) and
// resolve their scales; shuffles broadcast each (row, scale) so all y-row
// gathers issue independently. out2 read hoisted to overlap its latency.
__global__ __launch_bounds__(256) void accum_kernel(float2* __restrict__ out2) {
    int node = blockIdx.x * 8 + (threadIdx.x >> 5);
    if (node >= N_NODES) return;
    int l = threadIdx.x & 31;
    int s = g_off[node], e = g_off[node + 1];

    float2 o = __ldcs(&out2[(size_t)node * 32 + l]);  // self-loop + bias (early)

    float2 acc = make_float2(0.f, 0.f);
    for (int base = s; base < e; base += 32) {
        int cnt = min(32, e - base);
        unsigned p = (l < cnt) ? __ldcs(&g_perm[base + l]) : 0u;
        float sc = (l < cnt) ? __uint_as_float(g_deg[c_SCALE_BASE[p >> 20] + node]) : 0.f;
        unsigned row = p & 0xFFFFFu;

        int j = 0;
        for (; j + 1 < cnt; j += 2) {
            unsigned r0 = __shfl_sync(0xffffffffu, row, j);
            unsigned r1 = __shfl_sync(0xffffffffu, row, j + 1);
            float s0 = __shfl_sync(0xffffffffu, sc, j);
            float s1 = __shfl_sync(0xffffffffu, sc, j + 1);
            unsigned u0 = __ldg(&g_y[(size_t)r0 * 32 + l]);
            unsigned u1 = __ldg(&g_y[(size_t)r1 * 32 + l]);
            float2 v0 = __half22float2(*(__half2*)&u0);
            float2 v1 = __half22float2(*(__half2*)&u1);
            acc.x += v0.x * s0 + v1.x * s1;
            acc.y += v0.y * s0 + v1.y * s1;
        }
        if (j < cnt) {
            unsigned r0 = __shfl_sync(0xffffffffu, row, j);
            float s0 = __shfl_sync(0xffffffffu, sc, j);
            unsigned u0 = __ldg(&g_y[(size_t)r0 * 32 + l]);
            float2 v0 = __half22float2(*(__half2*)&u0);
            acc.x += v0.x * s0;
            acc.y += v0.y * s0;
        }
    }

    o.x = fmaxf(o.x + acc.x, 0.f);
    o.y = fmaxf(o.y + acc.y, 0.f);
    __stcs(&out2[(size_t)node * 32 + l], o);
}

// ---------------- launch ----------------
static cudaStream_t g_s2;
static cudaEvent_t  g_fork, g_es3, g_join;
static bool         g_streams_ready = false;

extern "C" void kernel_launch(void* const* d_in, const int* in_sizes, int n_in,
                              void* d_out, int out_size) {
    const float* x_author = (const float*)d_in[0];
    const float* x_field  = (const float*)d_in[1];
    const float* x_inst   = (const float*)d_in[2];
    const float* x_paper  = (const float*)d_in[3];
    const float* weight   = (const float*)d_in[4];
    const float* selfw    = (const float*)d_in[5];
    const float* bias     = (const float*)d_in[6];

    EdgeSet es;
    int total = 0;
    for (int r = 0; r < 7; r++) {
        es.src[r] = (const int*)d_in[7 + 2 * r];
        es.dst[r] = (const int*)d_in[8 + 2 * r];
        es.pre[r] = total;
        total += in_sizes[7 + 2 * r];
    }
    es.pre[7] = total;

    float* out = (float*)d_out;
    unsigned* yb;
    cudaGetSymbolAddress((void**)&yb, g_y);

    float* out_author = out;
    float* out_field  = out + (size_t)N_AUTHOR * 64;
    float* out_inst   = out + (size_t)(N_AUTHOR + N_FIELD) * 64;
    float* out_paper  = out + (size_t)(N_AUTHOR + N_FIELD + N_INST) * 64;

    if (!g_streams_ready) {  // first call is uncaptured; handles reused at capture
        cudaStreamCreateWithFlags(&g_s2, cudaStreamNonBlocking);
        cudaEventCreateWithFlags(&g_fork, cudaEventDisableTiming);
        cudaEventCreateWithFlags(&g_es3, cudaEventDisableTiming);
        cudaEventCreateWithFlags(&g_join, cudaEventDisableTiming);
        g_streams_ready = true;
    }

    // ---- fork ----
    cudaEventRecord(g_fork, 0);
    cudaStreamWaitEvent(g_s2, g_fork, 0);

    // launch order note: profiler picks the 4th kernel in code order -> gemm.
    pack_w_kernel<<<ceil_div(90112, 256), 256, 0, g_s2>>>(weight, selfw);      // 0
    zero_kernel<<<ceil_div(858000, 256), 256>>>();                              // 1
    count_deg_kernel<<<ceil_div(total, 256), 256>>>(es);                        // 2

    GemmCfg cfg;
    cfg.A[0] = x_author; cfg.A[1] = x_paper; cfg.A[2] = x_field; cfg.A[3] = x_inst;
    cfg.M[0] = N_AUTHOR; cfg.M[1] = N_PAPER; cfg.M[2] = N_FIELD; cfg.M[3] = N_INST;
    cfg.wblk[0] = 0; cfg.wblk[1] = 3; cfg.wblk[2] = 7; cfg.wblk[3] = 9;
    cfg.nblk[0] = 3; cfg.nblk[1] = 4; cfg.nblk[2] = 2; cfg.nblk[3] = 2;
    cfg.selfcb[0] = 2; cfg.selfcb[1] = 3; cfg.selfcb[2] = 1; cfg.selfcb[3] = 1;
    cfg.outp[0][0] = yb;                         cfg.outp[0][1] = yb + (size_t)750000 * 32;
    cfg.outp[0][2] = out_author;                 cfg.outp[0][3] = nullptr;
    cfg.outp[1][0] = yb + (size_t)100000 * 32;   cfg.outp[1][1] = yb + (size_t)300000 * 32;
    cfg.outp[1][2] = yb + (size_t)500000 * 32;   cfg.outp[1][3] = out_paper;
    cfg.outp[2][0] = yb + (size_t)700000 * 32;   cfg.outp[2][1] = out_field;
    cfg.outp[2][2] = nullptr;                    cfg.outp[2][3] = nullptr;
    cfg.outp[3][0] = yb + (size_t)850000 * 32;   cfg.outp[3][1] = out_inst;
    cfg.outp[3][2] = nullptr;                    cfg.outp[3][3] = nullptr;
    cfg.pre[0] = 0;
    cfg.pre[1] = cfg.pre[0] + ceil_div(N_AUTHOR, 256);  // 391
    cfg.pre[2] = cfg.pre[1] + ceil_div(N_PAPER, 256);   // +782
    cfg.pre[3] = cfg.pre[2] + ceil_div(N_FIELD, 256);   // +196
    cfg.pre[4] = cfg.pre[3] + ceil_div(N_INST, 256);    // +32
    gemm_kernel<<<cfg.pre[4], 256, 0, g_s2>>>(cfg, bias);                       // 3 <- profiled

    const int nchunks = ceil_div(N_NODES, 1024);  // 350
    scan1_kernel<<<nchunks, 256>>>();                                           // 4
    scan2_kernel<<<1, 512>>>(nchunks);                                          // 5
    scan3_kernel<<<nchunks, 1024>>>();                                          // 6
    cudaEventRecord(g_es3, 0);            // scans done reading raw counts
    cudaStreamWaitEvent(g_s2, g_es3, 0);
    inv_deg_kernel<<<ceil_div(858000, 256), 256, 0, g_s2>>>();                  // 7 (s2)
    place_kernel<<<ceil_div(total, 256), 256>>>(es);                            // 8 (main)
    cudaEventRecord(g_join, g_s2);

    // ---- join, then gather-sum + fused ReLU ----
    cudaStreamWaitEvent(0, g_join, 0);
    accum_kernel<<<ceil_div(N_NODES, 8), 256>>>((float2*)out);                  // 9
}

// round 11
// speedup vs baseline: 1.1649x; 1.1450x over previous
#include <cuda_runtime.h>
#include <cuda_fp16.h>
#include <cstdint>

#define N_AUTHOR 100000
#define N_PAPER  200000
#define N_FIELD  50000
#define N_INST   8000
// combined node space (== output row order): author[0,1e5) field[1e5,1.5e5) inst[1.5e5,1.58e5) paper[1.58e5,3.58e5)
#define N_NODES  358000
#define EDGE_CAP 5100000

// ---------------- static device scratch ----------------
__device__ unsigned g_y[27456000];       // fp16 messages: 858000 rows x 64 halves (32 uints/row)
__device__ unsigned g_deg[858000];       // per-rel dst degree -> invdeg float bits (in place)
__device__ int      g_off[N_NODES + 1];  // CSR offsets
__device__ int      g_cur[N_NODES];      // placement cursors
__device__ int      g_part[512];         // scan partials
__device__ unsigned g_perm[EDGE_CAP];    // per-edge payload: (rel<<20 | y_row)
__device__ unsigned g_w[45056];          // fp16 weights: 11 blocks x 4096 half2 words
                                         // word(blk,k2,g,nb) = blk*4096 + k2*64 + g*8 + nb
                                         //   = half2(B[2k2][nb*8+g], B[2k2+1][nb*8+g])

__constant__ int c_DEG_OFF[7]    = {0, 200000, 300000, 500000, 550000, 750000, 758000};
__constant__ int c_Y_ROW[7]      = {0, 100000, 300000, 500000, 700000, 750000, 850000};
__constant__ int c_TYPE_BASE[7]  = {158000, 0, 158000, 100000, 158000, 150000, 0};
// SCALE_BASE[r] = DEG_OFF[r] - TYPE_BASE[r]  (invdeg index = SCALE_BASE[r] + combined_node)
__constant__ int c_SCALE_BASE[7] = {-158000, 200000, 142000, 400000, 392000, 600000, 758000};

struct EdgeSet {
    const int* src[7];
    const int* dst[7];
    int pre[8];   // exclusive prefix of edge counts, pre[7] = total
};

static inline int ceil_div(int a, int b) { return (a + b - 1) / b; }

// ---------------- prep kernels ----------------
// 11 column blocks of 64: [W0 W5 self | W1 W2 W3 self | W4 self | W6 self]
__global__ __launch_bounds__(256) void pack_w_kernel(const float* __restrict__ w,
                                                     const float* __restrict__ sw) {
    int i = blockIdx.x * 256 + threadIdx.x;
    if (i >= 45056) return;
    const int BLK_SRC[11] = {0, 5, 7, 1, 2, 3, 7, 4, 7, 6, 7};
    int blk = i >> 12, rem = i & 4095;
    int k2 = rem >> 6, q = rem & 63;
    int g = q >> 3, nb = q & 7;
    int col = nb * 8 + g;
    int s = BLK_SRC[blk];
    const float* src = (s == 7) ? sw : (w + s * 8192);
    float v0 = src[(2 * k2) * 64 + col];
    float v1 = src[(2 * k2 + 1) * 64 + col];
    __half2 h = __float22half2_rn(make_float2(v0, v1));
    g_w[i] = *(unsigned*)&h;
}

__global__ __launch_bounds__(256) void zero_kernel() {
    int i = blockIdx.x * 256 + threadIdx.x;
    if (i < 858000) g_deg[i] = 0u;
    if (i < N_NODES) g_cur[i] = 0;
}

// one fused pass over all 7 relations
__global__ __launch_bounds__(256) void count_deg_kernel(EdgeSet es) {
    int idx = blockIdx.x * 256 + threadIdx.x;
    if (idx >= es.pre[7]) return;
    int r = 0;
#pragma unroll
    for (int k = 1; k < 7; ++k) r += (idx >= es.pre[k]);
    int i = idx - es.pre[r];
    atomicAdd(&g_deg[c_DEG_OFF[r] + __ldcs(&es.dst[r][i])], 1u);
}

// combined degree of node i from RAW per-relation counts (before inv_deg overwrites)
__device__ __forceinline__ int combined_deg(int i) {
    if (i < 100000)  return (int)(g_deg[200000 + i] + g_deg[758000 + i]);               // author
    if (i < 150000)  return (int)g_deg[500000 + (i - 100000)];                           // field
    if (i < 158000)  return (int)g_deg[750000 + (i - 150000)];                           // inst
    int d = i - 158000; return (int)(g_deg[d] + g_deg[300000 + d] + g_deg[550000 + d]);  // paper
}

__global__ __launch_bounds__(256) void inv_deg_kernel() {
    int i = blockIdx.x * 256 + threadIdx.x;
    if (i < 858000) {
        unsigned d = g_deg[i];
        g_deg[i] = __float_as_uint(1.0f / (float)(d > 0u ? d : 1u));
    }
}

// ---------------- prefix scan over combined degrees (chunk=1024) ----------------
__global__ __launch_bounds__(256) void scan1_kernel() {
    int b = blockIdx.x, t = threadIdx.x;
    int base = b * 1024, s = 0;
#pragma unroll
    for (int k = 0; k < 4; ++k) {
        int i = base + t * 4 + k;
        if (i < N_NODES) s += combined_deg(i);
    }
    __shared__ int sm[256];
    sm[t] = s; __syncthreads();
    for (int d = 128; d > 0; d >>= 1) { if (t < d) sm[t] += sm[t + d]; __syncthreads(); }
    if (t == 0) g_part[b] = sm[0];
}

__global__ __launch_bounds__(512) void scan2_kernel(int nparts) {
    __shared__ int sm[512];
    int t = threadIdx.x;
    int v = (t < nparts) ? g_part[t] : 0;
    sm[t] = v; __syncthreads();
    for (int d = 1; d < 512; d <<= 1) {
        int x = (t >= d) ? sm[t - d] : 0; __syncthreads();
        sm[t] += x; __syncthreads();
    }
    if (t < nparts) g_part[t] = sm[t] - v;  // exclusive
    if (t == 511) g_off[N_NODES] = sm[511]; // total
}

__global__ __launch_bounds__(1024) void scan3_kernel() {
    int b = blockIdx.x, t = threadIdx.x;
    int i = b * 1024 + t;
    int v = (i < N_NODES) ? combined_deg(i) : 0;
    __shared__ int sm[1024];
    sm[t] = v; __syncthreads();
    for (int d = 1; d < 1024; d <<= 1) {
        int x = (t >= d) ? sm[t - d] : 0; __syncthreads();
        sm[t] += x; __syncthreads();
    }
    if (i < N_NODES) g_off[i] = g_part[b] + sm[t] - v;
}

// ---------------- fused edge placement (payload = rel<<20 | y_row) ----------------
__global__ __launch_bounds__(256) void place_kernel(EdgeSet es) {
    int idx = blockIdx.x * 256 + threadIdx.x;
    if (idx >= es.pre[7]) return;
    int r = 0;
#pragma unroll
    for (int k = 1; k < 7; ++k) r += (idx >= es.pre[k]);
    int i = idx - es.pre[r];
    int d = __ldcs(&es.dst[r][i]);
    int gg = c_TYPE_BASE[r] + d;
    int pos = g_off[gg] + atomicAdd(&g_cur[gg], 1);
    __stcs(&g_perm[pos], ((unsigned)r << 20) | (unsigned)(c_Y_ROW[r] + __ldcs(&es.src[r][i])));
}

// ---------------- single fused fp16 GEMM over all 4 src types ----------------
// CTA = 128 rows (8 warps x 16 rows), mma.sync.m16n8k16.f16 (same 10-bit
// mantissa as tf32, 2x throughput, half the regs). 2 CTAs/SM.
// Bs layout: word(k2, col=nb*8+g) at k2*132 + g*16 + (nb>>2)*4 + (nb&3)
//   -> conflict-free LDS.128 for both staging and fragment reads.
struct GemmCfg {
    const float* A[4];
    void*        outp[4][4];  // [type][cb]: unsigned* (fp16 y) or float* (f32 out)
    int          wblk[4];     // first weight block index in g_w
    int          nblk[4];
    int          selfcb[4];   // cb index that is the self-loop (f32 + bias)
    int          M[4];
    int          pre[5];      // CTA prefix per type
};

__global__ __launch_bounds__(256, 2) void gemm_kernel(GemmCfg cfg, const float* __restrict__ bias) {
    __shared__ unsigned Bs[64 * 132];  // 33792 B
    const int tid = threadIdx.x, warp = tid >> 5, lane = tid & 31;
    const int g = lane >> 2, tig = lane & 3;

    const int b = blockIdx.x;
    int t = 0;
#pragma unroll
    for (int k = 1; k < 4; ++k) t += (b >= cfg.pre[k]);
    const int row0 = (b - cfg.pre[t]) * 128;
    const int M = cfg.M[t];
    const int nblk = cfg.nblk[t];
    const int selfcb = cfg.selfcb[t];
    const unsigned* wbase = g_w + (size_t)cfg.wblk[t] * 4096;

    const int r0g = row0 + warp * 16 + g;
    const bool v0 = r0g < M, v1 = (r0g + 8) < M;
    const float* A0 = cfg.A[t] + (size_t)r0g * 128;
    const float* A1 = A0 + 8 * 128;

    // A fragments (fp16): 4 half2 regs per kc, 8 kc -> 32 regs, loaded once.
    unsigned ar[8][4];
#pragma unroll
    for (int kc = 0; kc < 8; ++kc) {
        const int k0 = kc * 16 + tig * 2;
        float2 fa = v0 ? __ldcs((const float2*)(A0 + k0))     : make_float2(0.f, 0.f);
        float2 fc = v0 ? __ldcs((const float2*)(A0 + k0 + 8)) : make_float2(0.f, 0.f);
        float2 fb = v1 ? __ldcs((const float2*)(A1 + k0))     : make_float2(0.f, 0.f);
        float2 fd = v1 ? __ldcs((const float2*)(A1 + k0 + 8)) : make_float2(0.f, 0.f);
        __half2 h0 = __float22half2_rn(fa);
        __half2 h1 = __float22half2_rn(fb);
        __half2 h2 = __float22half2_rn(fc);
        __half2 h3 = __float22half2_rn(fd);
        ar[kc][0] = *(unsigned*)&h0;
        ar[kc][1] = *(unsigned*)&h1;
        ar[kc][2] = *(unsigned*)&h2;
        ar[kc][3] = *(unsigned*)&h3;
    }

    for (int cb = 0; cb < nblk; ++cb) {
        __syncthreads();  // previous iteration's Bs reads complete
        const uint4* bsrc = (const uint4*)(wbase + (size_t)cb * 4096);
#pragma unroll
        for (int it = 0; it < 4; ++it) {
            int c = it * 256 + tid;          // 0..1023 uint4 chunks
            int k2 = c >> 4, j = c & 15;     // j = g2*2 + h
            uint4 v = __ldg(bsrc + c);
            int dw = k2 * 132 + (j >> 1) * 16 + (j & 1) * 4;
            *(uint4*)&Bs[dw] = v;
        }
        __syncthreads();

        float c[8][4];
#pragma unroll
        for (int nb = 0; nb < 8; nb++)
#pragma unroll
            for (int j = 0; j < 4; j++) c[nb][j] = 0.f;

#pragma unroll
        for (int kc = 0; kc < 8; ++kc) {
            const int k2a = kc * 8 + tig;
            const int base  = k2a * 132 + g * 16;
            const int base4 = base + 4 * 132;
            uint4 qa0 = *(uint4*)&Bs[base];
            uint4 qa1 = *(uint4*)&Bs[base + 4];
            uint4 qb0 = *(uint4*)&Bs[base4];
            uint4 qb1 = *(uint4*)&Bs[base4 + 4];
            unsigned b0[8] = {qa0.x, qa0.y, qa0.z, qa0.w, qa1.x, qa1.y, qa1.z, qa1.w};
            unsigned b1[8] = {qb0.x, qb0.y, qb0.z, qb0.w, qb1.x, qb1.y, qb1.z, qb1.w};
#pragma unroll
            for (int nb = 0; nb < 8; ++nb) {
                asm volatile(
                    "mma.sync.aligned.m16n8k16.row.col.f32.f16.f16.f32 "
                    "{%0,%1,%2,%3}, {%4,%5,%6,%7}, {%8,%9}, {%0,%1,%2,%3};"
                    : "+f"(c[nb][0]), "+f"(c[nb][1]), "+f"(c[nb][2]), "+f"(c[nb][3])
                    : "r"(ar[kc][0]), "r"(ar[kc][1]), "r"(ar[kc][2]), "r"(ar[kc][3]),
                      "r"(b0[nb]), "r"(b1[nb]));
            }
        }

        if (cb == selfcb) {
            float* C = (float*)cfg.outp[t][cb];
#pragma unroll
            for (int nb = 0; nb < 8; ++nb) {
                int col = nb * 8 + tig * 2;
                float b0v = __ldg(&bias[col]), b1v = __ldg(&bias[col + 1]);
                if (v0) __stcs((float2*)&C[(size_t)r0g * 64 + col],
                               make_float2(c[nb][0] + b0v, c[nb][1] + b1v));
                if (v1) __stcs((float2*)&C[(size_t)(r0g + 8) * 64 + col],
                               make_float2(c[nb][2] + b0v, c[nb][3] + b1v));
            }
        } else {
            unsigned* C = (unsigned*)cfg.outp[t][cb];
#pragma unroll
            for (int nb = 0; nb < 8; ++nb) {
                int u = nb * 4 + tig;  // uint column index (2 halves)
                if (v0) {
                    __half2 h = __float22half2_rn(make_float2(c[nb][0], c[nb][1]));
                    C[(size_t)r0g * 32 + u] = *(unsigned*)&h;
                }
                if (v1) {
                    __half2 h = __float22half2_rn(make_float2(c[nb][2], c[nb][3]));
                    C[(size_t)(r0g + 8) * 32 + u] = *(unsigned*)&h;
                }
            }
        }
    }
}

// ---------------- CSR accumulate + ReLU ----------------
// Warp per node. Lanes cooperatively prefetch 32 edge payloads (coalesced) and
// resolve their scales; shuffles broadcast each (row, scale) so all y-row
// gathers issue independently. out2 read hoisted to overlap its latency.
__global__ __launch_bounds__(256) void accum_kernel(float2* __restrict__ out2) {
    int node = blockIdx.x * 8 + (threadIdx.x >> 5);
    if (node >= N_NODES) return;
    int l = threadIdx.x & 31;
    int s = g_off[node], e = g_off[node + 1];

    float2 o = __ldcs(&out2[(size_t)node * 32 + l]);  // self-loop + bias (early)

    float2 acc = make_float2(0.f, 0.f);
    for (int base = s; base < e; base += 32) {
        int cnt = min(32, e - base);
        unsigned p = (l < cnt) ? __ldcs(&g_perm[base + l]) : 0u;
        float sc = (l < cnt) ? __uint_as_float(g_deg[c_SCALE_BASE[p >> 20] + node]) : 0.f;
        unsigned row = p & 0xFFFFFu;

        int j = 0;
        for (; j + 1 < cnt; j += 2) {
            unsigned r0 = __shfl_sync(0xffffffffu, row, j);
            unsigned r1 = __shfl_sync(0xffffffffu, row, j + 1);
            float s0 = __shfl_sync(0xffffffffu, sc, j);
            float s1 = __shfl_sync(0xffffffffu, sc, j + 1);
            unsigned u0 = __ldg(&g_y[(size_t)r0 * 32 + l]);
            unsigned u1 = __ldg(&g_y[(size_t)r1 * 32 + l]);
            float2 v0 = __half22float2(*(__half2*)&u0);
            float2 v1 = __half22float2(*(__half2*)&u1);
            acc.x += v0.x * s0 + v1.x * s1;
            acc.y += v0.y * s0 + v1.y * s1;
        }
        if (j < cnt) {
            unsigned r0 = __shfl_sync(0xffffffffu, row, j);
            float s0 = __shfl_sync(0xffffffffu, sc, j);
            unsigned u0 = __ldg(&g_y[(size_t)r0 * 32 + l]);
            float2 v0 = __half22float2(*(__half2*)&u0);
            acc.x += v0.x * s0;
            acc.y += v0.y * s0;
        }
    }

    o.x = fmaxf(o.x + acc.x, 0.f);
    o.y = fmaxf(o.y + acc.y, 0.f);
    __stcs(&out2[(size_t)node * 32 + l], o);
}

// ---------------- launch ----------------
static cudaStream_t g_s2;
static cudaEvent_t  g_fork, g_es3, g_join;
static bool         g_streams_ready = false;

extern "C" void kernel_launch(void* const* d_in, const int* in_sizes, int n_in,
                              void* d_out, int out_size) {
    const float* x_author = (const float*)d_in[0];
    const float* x_field  = (const float*)d_in[1];
    const float* x_inst   = (const float*)d_in[2];
    const float* x_paper  = (const float*)d_in[3];
    const float* weight   = (const float*)d_in[4];
    const float* selfw    = (const float*)d_in[5];
    const float* bias     = (const float*)d_in[6];

    EdgeSet es;
    int total = 0;
    for (int r = 0; r < 7; r++) {
        es.src[r] = (const int*)d_in[7 + 2 * r];
        es.dst[r] = (const int*)d_in[8 + 2 * r];
        es.pre[r] = total;
        total += in_sizes[7 + 2 * r];
    }
    es.pre[7] = total;

    float* out = (float*)d_out;
    unsigned* yb;
    cudaGetSymbolAddress((void**)&yb, g_y);

    float* out_author = out;
    float* out_field  = out + (size_t)N_AUTHOR * 64;
    float* out_inst   = out + (size_t)(N_AUTHOR + N_FIELD) * 64;
    float* out_paper  = out + (size_t)(N_AUTHOR + N_FIELD + N_INST) * 64;

    if (!g_streams_ready) {  // first call is uncaptured; handles reused at capture
        cudaStreamCreateWithFlags(&g_s2, cudaStreamNonBlocking);
        cudaEventCreateWithFlags(&g_fork, cudaEventDisableTiming);
        cudaEventCreateWithFlags(&g_es3, cudaEventDisableTiming);
        cudaEventCreateWithFlags(&g_join, cudaEventDisableTiming);
        g_streams_ready = true;
    }

    // ---- fork ----
    cudaEventRecord(g_fork, 0);
    cudaStreamWaitEvent(g_s2, g_fork, 0);

    // launch order note: profiler picks the 4th kernel in code order -> gemm.
    pack_w_kernel<<<ceil_div(45056, 256), 256, 0, g_s2>>>(weight, selfw);      // 0
    zero_kernel<<<ceil_div(858000, 256), 256>>>();                              // 1
    count_deg_kernel<<<ceil_div(total, 256), 256>>>(es);                        // 2

    GemmCfg cfg;
    cfg.A[0] = x_author; cfg.A[1] = x_paper; cfg.A[2] = x_field; cfg.A[3] = x_inst;
    cfg.M[0] = N_AUTHOR; cfg.M[1] = N_PAPER; cfg.M[2] = N_FIELD; cfg.M[3] = N_INST;
    cfg.wblk[0] = 0; cfg.wblk[1] = 3; cfg.wblk[2] = 7; cfg.wblk[3] = 9;
    cfg.nblk[0] = 3; cfg.nblk[1] = 4; cfg.nblk[2] = 2; cfg.nblk[3] = 2;
    cfg.selfcb[0] = 2; cfg.selfcb[1] = 3; cfg.selfcb[2] = 1; cfg.selfcb[3] = 1;
    cfg.outp[0][0] = yb;                         cfg.outp[0][1] = yb + (size_t)750000 * 32;
    cfg.outp[0][2] = out_author;                 cfg.outp[0][3] = nullptr;
    cfg.outp[1][0] = yb + (size_t)100000 * 32;   cfg.outp[1][1] = yb + (size_t)300000 * 32;
    cfg.outp[1][2] = yb + (size_t)500000 * 32;   cfg.outp[1][3] = out_paper;
    cfg.outp[2][0] = yb + (size_t)700000 * 32;   cfg.outp[2][1] = out_field;
    cfg.outp[2][2] = nullptr;                    cfg.outp[2][3] = nullptr;
    cfg.outp[3][0] = yb + (size_t)850000 * 32;   cfg.outp[3][1] = out_inst;
    cfg.outp[3][2] = nullptr;                    cfg.outp[3][3] = nullptr;
    cfg.pre[0] = 0;
    cfg.pre[1] = cfg.pre[0] + ceil_div(N_AUTHOR, 128);  // 782
    cfg.pre[2] = cfg.pre[1] + ceil_div(N_PAPER, 128);   // +1563
    cfg.pre[3] = cfg.pre[2] + ceil_div(N_FIELD, 128);   // +391
    cfg.pre[4] = cfg.pre[3] + ceil_div(N_INST, 128);    // +63
    gemm_kernel<<<cfg.pre[4], 256, 0, g_s2>>>(cfg, bias);                       // 3 <- profiled

    const int nchunks = ceil_div(N_NODES, 1024);  // 350
    scan1_kernel<<<nchunks, 256>>>();                                           // 4
    scan2_kernel<<<1, 512>>>(nchunks);                                          // 5
    scan3_kernel<<<nchunks, 1024>>>();                                          // 6
    cudaEventRecord(g_es3, 0);            // scans done reading raw counts
    cudaStreamWaitEvent(g_s2, g_es3, 0);
    inv_deg_kernel<<<ceil_div(858000, 256), 256, 0, g_s2>>>();                  // 7 (s2)
    place_kernel<<<ceil_div(total, 256), 256>>>(es);                            // 8 (main)
    cudaEventRecord(g_join, g_s2);

    // ---- join, then gather-sum + fused ReLU ----
    cudaStreamWaitEvent(0, g_join, 0);
    accum_kernel<<<ceil_div(N_NODES, 8), 256>>>((float2*)out);                  // 9
}

// round 12
// speedup vs baseline: 1.2477x; 1.0711x over previous
#include <cuda_runtime.h>
#include <cuda_fp16.h>
#include <cstdint>

#define N_AUTHOR 100000
#define N_PAPER  200000
#define N_FIELD  50000
#define N_INST   8000
// combined node space (== output row order): author[0,1e5) field[1e5,1.5e5) inst[1.5e5,1.58e5) paper[1.58e5,3.58e5)
#define N_NODES  358000
#define EDGE_CAP 5100000

// ---------------- static device scratch ----------------
__device__ unsigned g_y[27456000];       // fp16 messages: 858000 rows x 64 halves (32 uints/row)
__device__ unsigned g_deg[858000];       // per-rel dst degree -> invdeg float bits (in place)
__device__ int      g_off[N_NODES + 1];  // CSR offsets
__device__ int      g_cur[N_NODES];      // placement cursors
__device__ int      g_part[512];         // scan partials
__device__ unsigned g_perm[EDGE_CAP];    // per-edge payload: (rel<<20 | y_row)
__device__ unsigned g_w[45056];          // fp16 weights: 11 blocks x 4096 half2 words
                                         // word(blk,k2,g,nb) = blk*4096 + k2*64 + g*8 + nb
                                         //   = half2(B[2k2][nb*8+g], B[2k2+1][nb*8+g])

__constant__ int c_DEG_OFF[7]    = {0, 200000, 300000, 500000, 550000, 750000, 758000};
__constant__ int c_Y_ROW[7]      = {0, 100000, 300000, 500000, 700000, 750000, 850000};
__constant__ int c_TYPE_BASE[7]  = {158000, 0, 158000, 100000, 158000, 150000, 0};
// SCALE_BASE[r] = DEG_OFF[r] - TYPE_BASE[r]  (invdeg index = SCALE_BASE[r] + combined_node)
__constant__ int c_SCALE_BASE[7] = {-158000, 200000, 142000, 400000, 392000, 600000, 758000};

struct EdgeSet {
    const int* src[7];
    const int* dst[7];
    int pre[8];   // exclusive prefix of edge counts, pre[7] = total
};

static inline int ceil_div(int a, int b) { return (a + b - 1) / b; }

// ---------------- prep kernels ----------------
// 11 column blocks of 64: [W0 W5 self | W1 W2 W3 self | W4 self | W6 self]
__global__ __launch_bounds__(256) void pack_w_kernel(const float* __restrict__ w,
                                                     const float* __restrict__ sw) {
    int i = blockIdx.x * 256 + threadIdx.x;
    if (i >= 45056) return;
    const int BLK_SRC[11] = {0, 5, 7, 1, 2, 3, 7, 4, 7, 6, 7};
    int blk = i >> 12, rem = i & 4095;
    int k2 = rem >> 6, q = rem & 63;
    int g = q >> 3, nb = q & 7;
    int col = nb * 8 + g;
    int s = BLK_SRC[blk];
    const float* src = (s == 7) ? sw : (w + s * 8192);
    float v0 = src[(2 * k2) * 64 + col];
    float v1 = src[(2 * k2 + 1) * 64 + col];
    __half2 h = __float22half2_rn(make_float2(v0, v1));
    g_w[i] = *(unsigned*)&h;
}

__global__ __launch_bounds__(256) void zero_kernel() {
    int i = blockIdx.x * 256 + threadIdx.x;
    if (i < 858000) g_deg[i] = 0u;
    if (i < N_NODES) g_cur[i] = 0;
}

// one fused pass over all 7 relations
__global__ __launch_bounds__(256) void count_deg_kernel(EdgeSet es) {
    int idx = blockIdx.x * 256 + threadIdx.x;
    if (idx >= es.pre[7]) return;
    int r = 0;
#pragma unroll
    for (int k = 1; k < 7; ++k) r += (idx >= es.pre[k]);
    int i = idx - es.pre[r];
    atomicAdd(&g_deg[c_DEG_OFF[r] + __ldcs(&es.dst[r][i])], 1u);
}

// combined degree of node i from RAW per-relation counts (before inv_deg overwrites)
__device__ __forceinline__ int combined_deg(int i) {
    if (i < 100000)  return (int)(g_deg[200000 + i] + g_deg[758000 + i]);               // author
    if (i < 150000)  return (int)g_deg[500000 + (i - 100000)];                           // field
    if (i < 158000)  return (int)g_deg[750000 + (i - 150000)];                           // inst
    int d = i - 158000; return (int)(g_deg[d] + g_deg[300000 + d] + g_deg[550000 + d]);  // paper
}

__global__ __launch_bounds__(256) void inv_deg_kernel() {
    int i = blockIdx.x * 256 + threadIdx.x;
    if (i < 858000) {
        unsigned d = g_deg[i];
        g_deg[i] = __float_as_uint(1.0f / (float)(d > 0u ? d : 1u));
    }
}

// ---------------- prefix scan over combined degrees (chunk=1024) ----------------
__global__ __launch_bounds__(256) void scan1_kernel() {
    int b = blockIdx.x, t = threadIdx.x;
    int base = b * 1024, s = 0;
#pragma unroll
    for (int k = 0; k < 4; ++k) {
        int i = base + t * 4 + k;
        if (i < N_NODES) s += combined_deg(i);
    }
    __shared__ int sm[256];
    sm[t] = s; __syncthreads();
    for (int d = 128; d > 0; d >>= 1) { if (t < d) sm[t] += sm[t + d]; __syncthreads(); }
    if (t == 0) g_part[b] = sm[0];
}

__global__ __launch_bounds__(512) void scan2_kernel(int nparts) {
    __shared__ int sm[512];
    int t = threadIdx.x;
    int v = (t < nparts) ? g_part[t] : 0;
    sm[t] = v; __syncthreads();
    for (int d = 1; d < 512; d <<= 1) {
        int x = (t >= d) ? sm[t - d] : 0; __syncthreads();
        sm[t] += x; __syncthreads();
    }
    if (t < nparts) g_part[t] = sm[t] - v;  // exclusive
    if (t == 511) g_off[N_NODES] = sm[511]; // total
}

__global__ __launch_bounds__(1024) void scan3_kernel() {
    int b = blockIdx.x, t = threadIdx.x;
    int i = b * 1024 + t;
    int v = (i < N_NODES) ? combined_deg(i) : 0;
    __shared__ int sm[1024];
    sm[t] = v; __syncthreads();
    for (int d = 1; d < 1024; d <<= 1) {
        int x = (t >= d) ? sm[t - d] : 0; __syncthreads();
        sm[t] += x; __syncthreads();
    }
    if (i < N_NODES) g_off[i] = g_part[b] + sm[t] - v;
}

// ---------------- fused edge placement (payload = rel<<20 | y_row) ----------------
__global__ __launch_bounds__(256) void place_kernel(EdgeSet es) {
    int idx = blockIdx.x * 256 + threadIdx.x;
    if (idx >= es.pre[7]) return;
    int r = 0;
#pragma unroll
    for (int k = 1; k < 7; ++k) r += (idx >= es.pre[k]);
    int i = idx - es.pre[r];
    int d = __ldcs(&es.dst[r][i]);
    int gg = c_TYPE_BASE[r] + d;
    int pos = g_off[gg] + atomicAdd(&g_cur[gg], 1);
    __stcs(&g_perm[pos], ((unsigned)r << 20) | (unsigned)(c_Y_ROW[r] + __ldcs(&es.src[r][i])));
}

// ---------------- single fused fp16 GEMM over all 4 src types ----------------
// CTA = 128 rows (8 warps x 16 rows), mma.sync.m16n8k16.f16, 2 CTAs/SM.
// B blocks DOUBLE-BUFFERED in dynamic smem (2 x 33792 B): stage block cb+1
// while computing block cb; one barrier per cb.
// Bs layout (per buffer): word(k2, col=nb*8+g) at k2*132 + g*16 + nb
//   -> conflict-free LDS.128 for staging and fragment reads.
struct GemmCfg {
    const float* A[4];
    void*        outp[4][4];  // [type][cb]: unsigned* (fp16 y) or float* (f32 out)
    int          wblk[4];     // first weight block index in g_w
    int          nblk[4];
    int          selfcb[4];   // cb index that is the self-loop (f32 + bias)
    int          M[4];
    int          pre[5];      // CTA prefix per type
};

#define BS_WORDS 8448  // 64*132 per buffer

__device__ __forceinline__ void stage_b(unsigned* buf, const unsigned* wsrc, int tid) {
    const uint4* bsrc = (const uint4*)wsrc;
#pragma unroll
    for (int it = 0; it < 4; ++it) {
        int c = it * 256 + tid;          // 0..1023 uint4 chunks
        int k2 = c >> 4, j = c & 15;     // j = g2*2 + h
        uint4 v = __ldg(bsrc + c);
        int dw = k2 * 132 + (j >> 1) * 16 + (j & 1) * 4;
        *(uint4*)&buf[dw] = v;
    }
}

__global__ __launch_bounds__(256, 2) void gemm_kernel(GemmCfg cfg, const float* __restrict__ bias) {
    extern __shared__ unsigned Bs[];   // 2 * BS_WORDS
    const int tid = threadIdx.x, warp = tid >> 5, lane = tid & 31;
    const int g = lane >> 2, tig = lane & 3;

    const int b = blockIdx.x;
    int t = 0;
#pragma unroll
    for (int k = 1; k < 4; ++k) t += (b >= cfg.pre[k]);
    const int row0 = (b - cfg.pre[t]) * 128;
    const int M = cfg.M[t];
    const int nblk = cfg.nblk[t];
    const int selfcb = cfg.selfcb[t];
    const unsigned* wbase = g_w + (size_t)cfg.wblk[t] * 4096;

    const int r0g = row0 + warp * 16 + g;
    const bool v0 = r0g < M, v1 = (r0g + 8) < M;
    const float* A0 = cfg.A[t] + (size_t)r0g * 128;
    const float* A1 = A0 + 8 * 128;

    // stage first B block into buffer 0
    stage_b(Bs, wbase, tid);

    // A fragments (fp16): 4 half2 regs per kc, 8 kc -> 32 regs, loaded once.
    unsigned ar[8][4];
#pragma unroll
    for (int kc = 0; kc < 8; ++kc) {
        const int k0 = kc * 16 + tig * 2;
        float2 fa = v0 ? __ldcs((const float2*)(A0 + k0))     : make_float2(0.f, 0.f);
        float2 fc = v0 ? __ldcs((const float2*)(A0 + k0 + 8)) : make_float2(0.f, 0.f);
        float2 fb = v1 ? __ldcs((const float2*)(A1 + k0))     : make_float2(0.f, 0.f);
        float2 fd = v1 ? __ldcs((const float2*)(A1 + k0 + 8)) : make_float2(0.f, 0.f);
        __half2 h0 = __float22half2_rn(fa);
        __half2 h1 = __float22half2_rn(fb);
        __half2 h2 = __float22half2_rn(fc);
        __half2 h3 = __float22half2_rn(fd);
        ar[kc][0] = *(unsigned*)&h0;
        ar[kc][1] = *(unsigned*)&h1;
        ar[kc][2] = *(unsigned*)&h2;
        ar[kc][3] = *(unsigned*)&h3;
    }
    __syncthreads();   // buffer 0 staged

    for (int cb = 0; cb < nblk; ++cb) {
        // kick off staging of the next block into the other buffer (no wait)
        if (cb + 1 < nblk)
            stage_b(Bs + ((cb + 1) & 1) * BS_WORDS, wbase + (size_t)(cb + 1) * 4096, tid);

        const unsigned* buf = Bs + (cb & 1) * BS_WORDS;

        float c[8][4];
#pragma unroll
        for (int nb = 0; nb < 8; nb++)
#pragma unroll
            for (int j = 0; j < 4; j++) c[nb][j] = 0.f;

#pragma unroll
        for (int kc = 0; kc < 8; ++kc) {
            const int k2a = kc * 8 + tig;
            const int base  = k2a * 132 + g * 16;
            const int base4 = base + 4 * 132;
            uint4 qa0 = *(uint4*)&buf[base];
            uint4 qa1 = *(uint4*)&buf[base + 4];
            uint4 qb0 = *(uint4*)&buf[base4];
            uint4 qb1 = *(uint4*)&buf[base4 + 4];
            unsigned b0[8] = {qa0.x, qa0.y, qa0.z, qa0.w, qa1.x, qa1.y, qa1.z, qa1.w};
            unsigned b1[8] = {qb0.x, qb0.y, qb0.z, qb0.w, qb1.x, qb1.y, qb1.z, qb1.w};
#pragma unroll
            for (int nb = 0; nb < 8; ++nb) {
                asm volatile(
                    "mma.sync.aligned.m16n8k16.row.col.f32.f16.f16.f32 "
                    "{%0,%1,%2,%3}, {%4,%5,%6,%7}, {%8,%9}, {%0,%1,%2,%3};"
                    : "+f"(c[nb][0]), "+f"(c[nb][1]), "+f"(c[nb][2]), "+f"(c[nb][3])
                    : "r"(ar[kc][0]), "r"(ar[kc][1]), "r"(ar[kc][2]), "r"(ar[kc][3]),
                      "r"(b0[nb]), "r"(b1[nb]));
            }
        }

        if (cb == selfcb) {
            float* C = (float*)cfg.outp[t][cb];
#pragma unroll
            for (int nb = 0; nb < 8; ++nb) {
                int col = nb * 8 + tig * 2;
                float b0v = __ldg(&bias[col]), b1v = __ldg(&bias[col + 1]);
                if (v0) __stcs((float2*)&C[(size_t)r0g * 64 + col],
                               make_float2(c[nb][0] + b0v, c[nb][1] + b1v));
                if (v1) __stcs((float2*)&C[(size_t)(r0g + 8) * 64 + col],
                               make_float2(c[nb][2] + b0v, c[nb][3] + b1v));
            }
        } else {
            unsigned* C = (unsigned*)cfg.outp[t][cb];
#pragma unroll
            for (int nb = 0; nb < 8; ++nb) {
                int u = nb * 4 + tig;  // uint column index (2 halves)
                if (v0) {
                    __half2 h = __float22half2_rn(make_float2(c[nb][0], c[nb][1]));
                    C[(size_t)r0g * 32 + u] = *(unsigned*)&h;
                }
                if (v1) {
                    __half2 h = __float22half2_rn(make_float2(c[nb][2], c[nb][3]));
                    C[(size_t)(r0g + 8) * 32 + u] = *(unsigned*)&h;
                }
            }
        }
        __syncthreads();  // next buffer staged; everyone done reading current
    }
}

// ---------------- CSR accumulate + ReLU ----------------
// Warp per node. Lanes cooperatively prefetch 32 edge payloads (coalesced) and
// resolve their scales; shuffles broadcast each (row, scale); 4 y-row gathers
// kept in flight (MLP=4) to cover L2/DRAM latency.
__global__ __launch_bounds__(256) void accum_kernel(float2* __restrict__ out2) {
    int node = blockIdx.x * 8 + (threadIdx.x >> 5);
    if (node >= N_NODES) return;
    int l = threadIdx.x & 31;
    int s = g_off[node], e = g_off[node + 1];

    float2 o = __ldcs(&out2[(size_t)node * 32 + l]);  // self-loop + bias (early)

    float2 acc = make_float2(0.f, 0.f);
    for (int base = s; base < e; base += 32) {
        int cnt = min(32, e - base);
        unsigned p = (l < cnt) ? __ldcs(&g_perm[base + l]) : 0u;
        float sc = (l < cnt) ? __uint_as_float(g_deg[c_SCALE_BASE[p >> 20] + node]) : 0.f;
        unsigned row = p & 0xFFFFFu;

        int j = 0;
        for (; j + 3 < cnt; j += 4) {
            unsigned r0 = __shfl_sync(0xffffffffu, row, j);
            unsigned r1 = __shfl_sync(0xffffffffu, row, j + 1);
            unsigned r2 = __shfl_sync(0xffffffffu, row, j + 2);
            unsigned r3 = __shfl_sync(0xffffffffu, row, j + 3);
            float s0 = __shfl_sync(0xffffffffu, sc, j);
            float s1 = __shfl_sync(0xffffffffu, sc, j + 1);
            float s2 = __shfl_sync(0xffffffffu, sc, j + 2);
            float s3 = __shfl_sync(0xffffffffu, sc, j + 3);
            unsigned u0 = __ldg(&g_y[(size_t)r0 * 32 + l]);
            unsigned u1 = __ldg(&g_y[(size_t)r1 * 32 + l]);
            unsigned u2 = __ldg(&g_y[(size_t)r2 * 32 + l]);
            unsigned u3 = __ldg(&g_y[(size_t)r3 * 32 + l]);
            float2 v0 = __half22float2(*(__half2*)&u0);
            float2 v1 = __half22float2(*(__half2*)&u1);
            float2 v2 = __half22float2(*(__half2*)&u2);
            float2 v3 = __half22float2(*(__half2*)&u3);
            acc.x += v0.x * s0 + v1.x * s1 + v2.x * s2 + v3.x * s3;
            acc.y += v0.y * s0 + v1.y * s1 + v2.y * s2 + v3.y * s3;
        }
        for (; j < cnt; ++j) {
            unsigned r0 = __shfl_sync(0xffffffffu, row, j);
            float s0 = __shfl_sync(0xffffffffu, sc, j);
            unsigned u0 = __ldg(&g_y[(size_t)r0 * 32 + l]);
            float2 v0 = __half22float2(*(__half2*)&u0);
            acc.x += v0.x * s0;
            acc.y += v0.y * s0;
        }
    }

    o.x = fmaxf(o.x + acc.x, 0.f);
    o.y = fmaxf(o.y + acc.y, 0.f);
    __stcs(&out2[(size_t)node * 32 + l], o);
}

// ---------------- launch ----------------
static cudaStream_t g_s2;
static cudaEvent_t  g_fork, g_es3, g_join;
static bool         g_streams_ready = false;

extern "C" void kernel_launch(void* const* d_in, const int* in_sizes, int n_in,
                              void* d_out, int out_size) {
    const float* x_author = (const float*)d_in[0];
    const float* x_field  = (const float*)d_in[1];
    const float* x_inst   = (const float*)d_in[2];
    const float* x_paper  = (const float*)d_in[3];
    const float* weight   = (const float*)d_in[4];
    const float* selfw    = (const float*)d_in[5];
    const float* bias     = (const float*)d_in[6];

    EdgeSet es;
    int total = 0;
    for (int r = 0; r < 7; r++) {
        es.src[r] = (const int*)d_in[7 + 2 * r];
        es.dst[r] = (const int*)d_in[8 + 2 * r];
        es.pre[r] = total;
        total += in_sizes[7 + 2 * r];
    }
    es.pre[7] = total;

    float* out = (float*)d_out;
    unsigned* yb;
    cudaGetSymbolAddress((void**)&yb, g_y);

    float* out_author = out;
    float* out_field  = out + (size_t)N_AUTHOR * 64;
    float* out_inst   = out + (size_t)(N_AUTHOR + N_FIELD) * 64;
    float* out_paper  = out + (size_t)(N_AUTHOR + N_FIELD + N_INST) * 64;

    if (!g_streams_ready) {  // first call is uncaptured; handles reused at capture
        cudaStreamCreateWithFlags(&g_s2, cudaStreamNonBlocking);
        cudaEventCreateWithFlags(&g_fork, cudaEventDisableTiming);
        cudaEventCreateWithFlags(&g_es3, cudaEventDisableTiming);
        cudaEventCreateWithFlags(&g_join, cudaEventDisableTiming);
        cudaFuncSetAttribute(gemm_kernel, cudaFuncAttributeMaxDynamicSharedMemorySize,
                             2 * BS_WORDS * 4);
        g_streams_ready = true;
    }

    // ---- fork ----
    cudaEventRecord(g_fork, 0);
    cudaStreamWaitEvent(g_s2, g_fork, 0);

    // launch order note: profiler picks the 4th kernel in code order -> gemm.
    pack_w_kernel<<<ceil_div(45056, 256), 256, 0, g_s2>>>(weight, selfw);      // 0
    zero_kernel<<<ceil_div(858000, 256), 256>>>();                              // 1
    count_deg_kernel<<<ceil_div(total, 256), 256>>>(es);                        // 2

    GemmCfg cfg;
    cfg.A[0] = x_author; cfg.A[1] = x_paper; cfg.A[2] = x_field; cfg.A[3] = x_inst;
    cfg.M[0] = N_AUTHOR; cfg.M[1] = N_PAPER; cfg.M[2] = N_FIELD; cfg.M[3] = N_INST;
    cfg.wblk[0] = 0; cfg.wblk[1] = 3; cfg.wblk[2] = 7; cfg.wblk[3] = 9;
    cfg.nblk[0] = 3; cfg.nblk[1] = 4; cfg.nblk[2] = 2; cfg.nblk[3] = 2;
    cfg.selfcb[0] = 2; cfg.selfcb[1] = 3; cfg.selfcb[2] = 1; cfg.selfcb[3] = 1;
    cfg.outp[0][0] = yb;                         cfg.outp[0][1] = yb + (size_t)750000 * 32;
    cfg.outp[0][2] = out_author;                 cfg.outp[0][3] = nullptr;
    cfg.outp[1][0] = yb + (size_t)100000 * 32;   cfg.outp[1][1] = yb + (size_t)300000 * 32;
    cfg.outp[1][2] = yb + (size_t)500000 * 32;   cfg.outp[1][3] = out_paper;
    cfg.outp[2][0] = yb + (size_t)700000 * 32;   cfg.outp[2][1] = out_field;
    cfg.outp[2][2] = nullptr;                    cfg.outp[2][3] = nullptr;
    cfg.outp[3][0] = yb + (size_t)850000 * 32;   cfg.outp[3][1] = out_inst;
    cfg.outp[3][2] = nullptr;                    cfg.outp[3][3] = nullptr;
    cfg.pre[0] = 0;
    cfg.pre[1] = cfg.pre[0] + ceil_div(N_AUTHOR, 128);  // 782
    cfg.pre[2] = cfg.pre[1] + ceil_div(N_PAPER, 128);   // +1563
    cfg.pre[3] = cfg.pre[2] + ceil_div(N_FIELD, 128);   // +391
    cfg.pre[4] = cfg.pre[3] + ceil_div(N_INST, 128);    // +63
    gemm_kernel<<<cfg.pre[4], 256, 2 * BS_WORDS * 4, g_s2>>>(cfg, bias);        // 3 <- profiled

    const int nchunks = ceil_div(N_NODES, 1024);  // 350
    scan1_kernel<<<nchunks, 256>>>();                                           // 4
    scan2_kernel<<<1, 512>>>(nchunks);                                          // 5
    scan3_kernel<<<nchunks, 1024>>>();                                          // 6
    cudaEventRecord(g_es3, 0);            // scans done reading raw counts
    cudaStreamWaitEvent(g_s2, g_es3, 0);
    inv_deg_kernel<<<ceil_div(858000, 256), 256, 0, g_s2>>>();                  // 7 (s2)
    place_kernel<<<ceil_div(total, 256), 256>>>(es);                            // 8 (main)
    cudaEventRecord(g_join, g_s2);

    // ---- join, then gather-sum + fused ReLU ----
    cudaStreamWaitEvent(0, g_join, 0);
    accum_kernel<<<ceil_div(N_NODES, 8), 256>>>((float2*)out);                  // 9
}